// round 9
// baseline (speedup 1.0000x reference)
#include <cuda_runtime.h>
#include <cuda_bf16.h>
#include <cstdint>

// Problem constants (fixed shapes for this problem)
#define MAXN 100000
#define MAXE 1600000
#define DIM  64
#define MAXG 512

// ---------------- scratch (static device globals; no allocation allowed) ----
// Contiguous zero-init block: one cudaMemsetAsync clears everything.
struct ClearBlock {
    int   cnt[MAXN];            // in-degree counts (excl self loop)
    float hsum[MAXG * DIM];
    float hmax[MAXG * DIM];
    int   gcnt[MAXG];
};
__device__ ClearBlock g_clr;

__device__ int   g_rowptr[MAXN + 1];   // CSR row pointers (by dst)
__device__ int   g_cursor[MAXN];       // scatter cursors
__device__ float g_dinv[MAXN];         // deg^-0.5 (deg incl self loop)
__device__ int   g_esrc[MAXE];         // CSR column (src) indices
__device__ float g_z[(size_t)MAXN * DIM];   // z = dinv * (x @ W), fp32
__device__ float g_xa[(size_t)MAXN * DIM];  // feature ping
__device__ float g_xb[(size_t)MAXN * DIM];  // feature pong

// ---------------- small helpers --------------------------------------------
__device__ __forceinline__ void fma2(unsigned long long& d, unsigned long long a,
                                     unsigned long long b) {
    asm("fma.rn.f32x2 %0, %1, %2, %0;" : "+l"(d) : "l"(a), "l"(b));
}
__device__ __forceinline__ unsigned long long pack2(float x) {
    unsigned long long r;
    asm("mov.b64 %0, {%1, %1};" : "=l"(r) : "f"(x));
    return r;
}
__device__ __forceinline__ float2 unpack2(unsigned long long v) {
    float2 f;
    asm("mov.b64 {%0, %1}, %2;" : "=f"(f.x), "=f"(f.y) : "l"(v));
    return f;
}

// ---------------- CSR build ------------------------------------------------
__global__ void k_count(const int* __restrict__ dst, int e) {
    int i = blockIdx.x * blockDim.x + threadIdx.x;
    if (i < e) atomicAdd(&g_clr.cnt[dst[i]], 1);
}

// Single-block exclusive scan over counts -> rowptr/cursor, plus dinv.
// 1024 threads, each handles a contiguous run of ceil(n/1024) elements.
__global__ void __launch_bounds__(1024, 1)
k_scan_all(int n) {
    int t = threadIdx.x;
    int C = (n + 1023) >> 10;
    int beg = t * C;
    int end = beg + C; if (end > n) end = n;
    if (beg > n) beg = n;

    int s = 0;
    for (int i = beg; i < end; i++) s += g_clr.cnt[i];

    int lane = t & 31, wid = t >> 5;
    int x = s;
#pragma unroll
    for (int o = 1; o < 32; o <<= 1) {
        int y = __shfl_up_sync(0xffffffffu, x, o);
        if (lane >= o) x += y;
    }
    __shared__ int wsum[32];
    __shared__ int woff[32];
    if (lane == 31) wsum[wid] = x;
    __syncthreads();
    if (wid == 0) {
        int v = wsum[lane];
        int inc = v;
#pragma unroll
        for (int o = 1; o < 32; o <<= 1) {
            int y = __shfl_up_sync(0xffffffffu, inc, o);
            if (lane >= o) inc += y;
        }
        woff[lane] = inc - v;
    }
    __syncthreads();
    int off = woff[wid] + (x - s);   // exclusive prefix for this thread's run

    int run = off;
    for (int i = beg; i < end; i++) {
        int c = g_clr.cnt[i];
        g_rowptr[i] = run;
        g_cursor[i] = run;
        g_dinv[i] = rsqrtf((float)(c + 1));  // +1 self loop
        run += c;
    }
    if (t == 1023) g_rowptr[n] = off + s;    // total edge count
}

__global__ void k_scatter(const int* __restrict__ src, const int* __restrict__ dst, int e) {
    int i = blockIdx.x * blockDim.x + threadIdx.x;
    if (i < e) {
        int d = dst[i];
        int p = atomicAdd(&g_cursor[d], 1);
        g_esrc[p] = src[i];
    }
}

// ---------------- fused GEMM: z = dinv[i] * (x_i @ W) ----------------------
// block = 256 threads; block tile = 256 rows x 64 cols;
// thread = 4 rows x 16 cols, accumulators packed as f32x2 (exact fp32 math).
__global__ void __launch_bounds__(256, 2)
k_gemm(const float* __restrict__ X, const int* __restrict__ tokens,
       const float* __restrict__ emb, const float* __restrict__ W,
       float* __restrict__ Z, int n) {
    __shared__ float Ws[DIM * DIM];
    int t = threadIdx.x;
    for (int i = t; i < DIM * DIM / 4; i += 256)
        ((float4*)Ws)[i] = ((const float4*)W)[i];
    __syncthreads();

    int rg = blockIdx.x * 64 + (t >> 2);   // row-group of 4 rows
    int r0 = rg * 4;
    if (r0 >= n) return;
    int cg = (t & 3) * 16;                 // first column of this thread

    const float* xr[4];
#pragma unroll
    for (int r = 0; r < 4; r++) {
        int rowc = r0 + r;
        int rr = rowc < n ? rowc : (n - 1);
        xr[r] = tokens ? (emb + (size_t)__ldg(tokens + rr) * DIM)
                       : (X + (size_t)rr * DIM);
    }

    unsigned long long acc[4][8];
#pragma unroll
    for (int r = 0; r < 4; r++)
#pragma unroll
        for (int j = 0; j < 8; j++) acc[r][j] = 0ull;

#pragma unroll
    for (int k = 0; k < DIM; k += 4) {
        float4 xv0 = *(const float4*)(xr[0] + k);
        float4 xv1 = *(const float4*)(xr[1] + k);
        float4 xv2 = *(const float4*)(xr[2] + k);
        float4 xv3 = *(const float4*)(xr[3] + k);
#pragma unroll
        for (int kk = 0; kk < 4; kk++) {
            const ulonglong2* wp = (const ulonglong2*)(Ws + (k + kk) * DIM + cg);
            ulonglong2 wa = wp[0], wb = wp[1], wc = wp[2], wd = wp[3];
            unsigned long long x0 = pack2((&xv0.x)[kk]);
            unsigned long long x1 = pack2((&xv1.x)[kk]);
            unsigned long long x2 = pack2((&xv2.x)[kk]);
            unsigned long long x3 = pack2((&xv3.x)[kk]);
            fma2(acc[0][0], x0, wa.x); fma2(acc[0][1], x0, wa.y);
            fma2(acc[0][2], x0, wb.x); fma2(acc[0][3], x0, wb.y);
            fma2(acc[0][4], x0, wc.x); fma2(acc[0][5], x0, wc.y);
            fma2(acc[0][6], x0, wd.x); fma2(acc[0][7], x0, wd.y);
            fma2(acc[1][0], x1, wa.x); fma2(acc[1][1], x1, wa.y);
            fma2(acc[1][2], x1, wb.x); fma2(acc[1][3], x1, wb.y);
            fma2(acc[1][4], x1, wc.x); fma2(acc[1][5], x1, wc.y);
            fma2(acc[1][6], x1, wd.x); fma2(acc[1][7], x1, wd.y);
            fma2(acc[2][0], x2, wa.x); fma2(acc[2][1], x2, wa.y);
            fma2(acc[2][2], x2, wb.x); fma2(acc[2][3], x2, wb.y);
            fma2(acc[2][4], x2, wc.x); fma2(acc[2][5], x2, wc.y);
            fma2(acc[2][6], x2, wd.x); fma2(acc[2][7], x2, wd.y);
            fma2(acc[3][0], x3, wa.x); fma2(acc[3][1], x3, wa.y);
            fma2(acc[3][2], x3, wb.x); fma2(acc[3][3], x3, wb.y);
            fma2(acc[3][4], x3, wc.x); fma2(acc[3][5], x3, wc.y);
            fma2(acc[3][6], x3, wd.x); fma2(acc[3][7], x3, wd.y);
        }
    }

#pragma unroll
    for (int r = 0; r < 4; r++) {
        int rowc = r0 + r;
        if (rowc >= n) break;
        float dv = g_dinv[rowc];
        float* zr = Z + (size_t)rowc * DIM + cg;
#pragma unroll
        for (int j = 0; j < 8; j += 2) {
            float2 f0 = unpack2(acc[r][j]);
            float2 f1 = unpack2(acc[r][j + 1]);
            float4 o;
            o.x = f0.x * dv; o.y = f0.y * dv;
            o.z = f1.x * dv; o.w = f1.y * dv;
            *(float4*)(zr + j * 2) = o;
        }
    }
}

// ---------------- gather: x_out[i] = relu(dinv[i]*(z[i] + sum z[src]) + b) --
// warp per destination node; lane covers 2 feature dims as float2
__global__ void k_gather(const float* __restrict__ Z, const float* __restrict__ b,
                         float* __restrict__ Xo, int n) {
    int w = (int)((blockIdx.x * blockDim.x + threadIdx.x) >> 5);
    if (w >= n) return;
    int lane = threadIdx.x & 31;
    int beg = g_rowptr[w], end = g_rowptr[w + 1];
    const float2* zc = (const float2*)Z;        // node row = 32 float2
    float2 acc = zc[(size_t)w * 32 + lane];     // self loop
    for (int e0 = beg; e0 < end; e0 += 32) {
        int c = end - e0; if (c > 32) c = 32;
        int s = (lane < c) ? g_esrc[e0 + lane] : 0;
        int j = 0;
        for (; j + 4 <= c; j += 4) {
            int s0 = __shfl_sync(0xffffffffu, s, j);
            int s1 = __shfl_sync(0xffffffffu, s, j + 1);
            int s2 = __shfl_sync(0xffffffffu, s, j + 2);
            int s3 = __shfl_sync(0xffffffffu, s, j + 3);
            float2 v0 = zc[(size_t)s0 * 32 + lane];
            float2 v1 = zc[(size_t)s1 * 32 + lane];
            float2 v2 = zc[(size_t)s2 * 32 + lane];
            float2 v3 = zc[(size_t)s3 * 32 + lane];
            acc.x += (v0.x + v1.x) + (v2.x + v3.x);
            acc.y += (v0.y + v1.y) + (v2.y + v3.y);
        }
        for (; j < c; j++) {
            int sj = __shfl_sync(0xffffffffu, s, j);
            float2 v = zc[(size_t)sj * 32 + lane];
            acc.x += v.x; acc.y += v.y;
        }
    }
    float dv = g_dinv[w];
    int col = lane * 2;
    float2 o;
    o.x = fmaxf(fmaf(dv, acc.x, __ldg(b + col)),     0.f);
    o.y = fmaxf(fmaf(dv, acc.y, __ldg(b + col + 1)), 0.f);
    ((float2*)Xo)[(size_t)w * 32 + lane] = o;
}

// ---------------- pooling (batch sorted): run-accumulate, flush on boundary -
__global__ void k_pool(const float* __restrict__ X, const int* __restrict__ batch, int n) {
    int w = (int)((blockIdx.x * blockDim.x + threadIdx.x) >> 5);
    int lane = threadIdx.x & 31;
    int base = w * 32;
    if (base >= n) return;
    int myb = (base + lane < n) ? batch[base + lane] : 0;
    const float2* xc = (const float2*)X;
    float2 s = make_float2(0.f, 0.f), m = make_float2(0.f, 0.f);
    int curg = __shfl_sync(0xffffffffu, myb, 0);
    int rc = 0;
    for (int j = 0; j < 32; j++) {
        int node = base + j;
        if (node >= n) break;
        int g = __shfl_sync(0xffffffffu, myb, j);
        if (g != curg) {
            atomicAdd(&g_clr.hsum[curg * DIM + lane * 2],     s.x);
            atomicAdd(&g_clr.hsum[curg * DIM + lane * 2 + 1], s.y);
            atomicMax((int*)&g_clr.hmax[curg * DIM + lane * 2],     __float_as_int(m.x));
            atomicMax((int*)&g_clr.hmax[curg * DIM + lane * 2 + 1], __float_as_int(m.y));
            if (lane == 0) atomicAdd(&g_clr.gcnt[curg], rc);
            s = make_float2(0.f, 0.f); m = make_float2(0.f, 0.f); rc = 0; curg = g;
        }
        float2 v = xc[(size_t)node * 32 + lane];
        s.x += v.x; s.y += v.y;
        m.x = fmaxf(m.x, v.x); m.y = fmaxf(m.y, v.y);
        rc++;
    }
    if (rc) {
        atomicAdd(&g_clr.hsum[curg * DIM + lane * 2],     s.x);
        atomicAdd(&g_clr.hsum[curg * DIM + lane * 2 + 1], s.y);
        atomicMax((int*)&g_clr.hmax[curg * DIM + lane * 2],     __float_as_int(m.x));
        atomicMax((int*)&g_clr.hmax[curg * DIM + lane * 2 + 1], __float_as_int(m.y));
        if (lane == 0) atomicAdd(&g_clr.gcnt[curg], rc);
    }
}

// ---------------- classifier head ------------------------------------------
__global__ void k_mlp(const float* __restrict__ Wc1, const float* __restrict__ bc1,
                      const float* __restrict__ Wc2, const float* __restrict__ bc2,
                      float* __restrict__ out) {
    __shared__ float h[2 * DIM];
    __shared__ float r[4];
    int g = blockIdx.x, t = threadIdx.x;  // 64 threads
    float cnt = fmaxf((float)g_clr.gcnt[g], 1.f);
    h[t]       = g_clr.hsum[g * DIM + t] / cnt;
    h[DIM + t] = g_clr.hmax[g * DIM + t];
    __syncthreads();
    float acc = bc1[t];
#pragma unroll 8
    for (int k = 0; k < 2 * DIM; k++) acc = fmaf(h[k], Wc1[k * DIM + t], acc);
    acc = fmaxf(acc, 0.f);
    float p0 = acc * Wc2[t * 2], p1 = acc * Wc2[t * 2 + 1];
#pragma unroll
    for (int o = 16; o; o >>= 1) {
        p0 += __shfl_down_sync(0xffffffffu, p0, o);
        p1 += __shfl_down_sync(0xffffffffu, p1, o);
    }
    if ((t & 31) == 0) { r[(t >> 5) * 2] = p0; r[(t >> 5) * 2 + 1] = p1; }
    __syncthreads();
    if (t == 0) {
        out[g * 2 + 0] = r[0] + r[2] + bc2[0];
        out[g * 2 + 1] = r[1] + r[3] + bc2[1];
    }
}

// ---------------- launcher --------------------------------------------------
extern "C" void kernel_launch(void* const* d_in, const int* in_sizes, int n_in,
                              void* d_out, int out_size) {
    const int*   tokens = (const int*)d_in[0];
    const int*   eidx   = (const int*)d_in[1];
    const int*   batch  = (const int*)d_in[2];
    const float* emb    = (const float*)d_in[3];
    const float* W0 = (const float*)d_in[4];  const float* b0 = (const float*)d_in[5];
    const float* W1 = (const float*)d_in[6];  const float* b1 = (const float*)d_in[7];
    const float* W2 = (const float*)d_in[8];  const float* b2 = (const float*)d_in[9];
    const float* Wc1 = (const float*)d_in[10]; const float* bc1 = (const float*)d_in[11];
    const float* Wc2 = (const float*)d_in[12]; const float* bc2 = (const float*)d_in[13];

    int n  = in_sizes[0];
    int e  = in_sizes[1] / 2;
    int Gn = out_size / 2;
    if (n > MAXN) n = MAXN;
    if (e > MAXE) e = MAXE;
    if (Gn > MAXG) Gn = MAXG;

    void *p_clr, *p_z, *p_xa, *p_xb;
    cudaGetSymbolAddress(&p_clr, g_clr);
    cudaGetSymbolAddress(&p_z,  g_z);
    cudaGetSymbolAddress(&p_xa, g_xa);
    cudaGetSymbolAddress(&p_xb, g_xb);
    float* Z  = (float*)p_z;
    float* XA = (float*)p_xa;
    float* XB = (float*)p_xb;

    // One contiguous clear of cnt + hsum + hmax + gcnt
    cudaMemsetAsync(p_clr, 0, sizeof(ClearBlock));

    const int* src = eidx;
    const int* dst = eidx + e;

    int eb = (e + 255) / 256;
    k_count<<<eb, 256>>>(dst, e);
    k_scan_all<<<1, 1024>>>(n);
    k_scatter<<<eb, 256>>>(src, dst, e);

    int gb = (n + 255) / 256;  // gemm blocks (256 rows per block)
    int wb = (n + 7) / 8;      // warp-per-node blocks (8 warps/block)

    k_gemm<<<gb, 256>>>(nullptr, tokens, emb, W0, Z, n);
    k_gather<<<wb, 256>>>(Z, b0, XA, n);
    k_gemm<<<gb, 256>>>(XA, nullptr, nullptr, W1, Z, n);
    k_gather<<<wb, 256>>>(Z, b1, XB, n);
    k_gemm<<<gb, 256>>>(XB, nullptr, nullptr, W2, Z, n);
    k_gather<<<wb, 256>>>(Z, b2, XA, n);

    int pw = (n + 31) / 32;
    k_pool<<<(pw + 7) / 8, 256>>>(XA, batch, n);
    k_mlp<<<Gn, 64>>>(Wc1, bc1, Wc2, bc2, (float*)d_out);
}

// round 10
// speedup vs baseline: 1.8000x; 1.8000x over previous
#include <cuda_runtime.h>
#include <cuda_bf16.h>
#include <cuda_fp16.h>
#include <cstdint>

// Problem constants (fixed shapes for this problem)
#define MAXN 100000
#define MAXE 1600000
#define DIM  64
#define MAXG 512
#define SCAN_CHUNK 1024

#define ZSCALE   16384.0f          // 2^14: lifts z out of fp16 subnormal range
#define ZUNSCALE (1.0f / 16384.0f) // exact power of two

// ---------------- scratch (static device globals; no allocation allowed) ----
// Contiguous zero-init block: one cudaMemsetAsync clears everything.
struct ClearBlock {
    int   cnt[MAXN];            // in-degree counts (excl self loop)
    float hsum[MAXG * DIM];
    float hmax[MAXG * DIM];
    int   gcnt[MAXG];
};
__device__ ClearBlock g_clr;

__device__ int      g_rowptr[MAXN + 1];   // CSR row pointers (by dst)
__device__ int      g_cursor[MAXN];       // scatter cursors
__device__ float    g_dinv[MAXN];         // deg^-0.5 (deg incl self loop)
__device__ int      g_esrc[MAXE];         // CSR column (src) indices
__device__ int      g_bsum[(MAXN + SCAN_CHUNK - 1) / SCAN_CHUNK + 1];
__device__ uint32_t g_z[(size_t)MAXN * (DIM / 2)];  // z scaled fp16 (half2 words)
__device__ float    g_xa[(size_t)MAXN * DIM];       // feature ping (fp32)
__device__ float    g_xb[(size_t)MAXN * DIM];       // feature pong (fp32)

// ---------------- small helpers --------------------------------------------
__device__ __forceinline__ void fma2(unsigned long long& d, unsigned long long a,
                                     unsigned long long b) {
    asm("fma.rn.f32x2 %0, %1, %2, %0;" : "+l"(d) : "l"(a), "l"(b));
}
__device__ __forceinline__ unsigned long long pack2(float x) {
    unsigned long long r;
    asm("mov.b64 %0, {%1, %1};" : "=l"(r) : "f"(x));
    return r;
}
__device__ __forceinline__ float2 unpack2(unsigned long long v) {
    float2 f;
    asm("mov.b64 {%0, %1}, %2;" : "=f"(f.x), "=f"(f.y) : "l"(v));
    return f;
}
__device__ __forceinline__ float2 h2_to_f2(uint32_t u) {
    __half2 h = *reinterpret_cast<__half2*>(&u);
    return __half22float2(h);
}
__device__ __forceinline__ uint32_t f2_to_h2(float a, float b) {
    __half2 h = __floats2half2_rn(a, b);
    return *reinterpret_cast<uint32_t*>(&h);
}

// ---------------- CSR build (coalesced multi-block ladder) ------------------
__global__ void k_count(const int* __restrict__ dst, int e) {
    int i = blockIdx.x * blockDim.x + threadIdx.x;
    if (i < e) atomicAdd(&g_clr.cnt[dst[i]], 1);
}

__global__ void k_scan1(int n) {  // per-1024-chunk sums
    int t = threadIdx.x;
    int base = blockIdx.x * SCAN_CHUNK + t * 4;
    int s = 0;
#pragma unroll
    for (int j = 0; j < 4; j++) if (base + j < n) s += g_clr.cnt[base + j];
#pragma unroll
    for (int o = 16; o; o >>= 1) s += __shfl_down_sync(0xffffffffu, s, o);
    __shared__ int ws[8];
    if ((t & 31) == 0) ws[t >> 5] = s;
    __syncthreads();
    if (t == 0) {
        int tot = 0;
#pragma unroll
        for (int i = 0; i < 8; i++) tot += ws[i];
        g_bsum[blockIdx.x] = tot;
    }
}

__global__ void k_scan2(int nb, int n) {  // tiny serial scan of chunk sums
    int run = 0;
    for (int i = 0; i < nb; i++) { int v = g_bsum[i]; g_bsum[i] = run; run += v; }
    g_rowptr[n] = run;
}

__global__ void k_scan3(int n) {  // per-chunk exclusive scan -> rowptr/cursor
    int t = threadIdx.x;
    int lane = t & 31, wid = t >> 5;
    int base = blockIdx.x * SCAN_CHUNK + t * 4;
    int c0 = (base + 0 < n) ? g_clr.cnt[base + 0] : 0;
    int c1 = (base + 1 < n) ? g_clr.cnt[base + 1] : 0;
    int c2 = (base + 2 < n) ? g_clr.cnt[base + 2] : 0;
    int c3 = (base + 3 < n) ? g_clr.cnt[base + 3] : 0;
    int ts = c0 + c1 + c2 + c3;
    int x = ts;
#pragma unroll
    for (int o = 1; o < 32; o <<= 1) {
        int y = __shfl_up_sync(0xffffffffu, x, o);
        if (lane >= o) x += y;
    }
    int wex = x - ts;  // exclusive within warp
    __shared__ int warpsums[8];
    if (lane == 31) warpsums[wid] = x;
    __syncthreads();
    int woff = 0;
    for (int i = 0; i < wid; i++) woff += warpsums[i];
    int off = g_bsum[blockIdx.x] + woff + wex;
    if (base + 0 < n) { g_rowptr[base + 0] = off;             g_cursor[base + 0] = off; }
    if (base + 1 < n) { g_rowptr[base + 1] = off + c0;        g_cursor[base + 1] = off + c0; }
    if (base + 2 < n) { g_rowptr[base + 2] = off + c0 + c1;   g_cursor[base + 2] = off + c0 + c1; }
    if (base + 3 < n) { g_rowptr[base + 3] = off + c0 + c1 + c2; g_cursor[base + 3] = off + c0 + c1 + c2; }
}

__global__ void k_dinv(int n) {
    int i = blockIdx.x * blockDim.x + threadIdx.x;
    if (i < n) g_dinv[i] = rsqrtf((float)(g_clr.cnt[i] + 1));  // +1 self loop
}

__global__ void k_scatter(const int* __restrict__ src, const int* __restrict__ dst, int e) {
    int i = blockIdx.x * blockDim.x + threadIdx.x;
    if (i < e) {
        int d = dst[i];
        int p = atomicAdd(&g_cursor[d], 1);
        g_esrc[p] = src[i];
    }
}

// ---------------- fused GEMM: z = fp16( ZSCALE * dinv[i] * (x_i @ W) ) ------
// block = 256 threads; block tile = 256 rows x 64 cols;
// thread = 4 rows x 16 cols, accumulators packed as f32x2 (exact fp32 math).
__global__ void __launch_bounds__(256, 2)
k_gemm(const float* __restrict__ X, const int* __restrict__ tokens,
       const float* __restrict__ emb, const float* __restrict__ W,
       uint32_t* __restrict__ Z, int n) {
    __shared__ float Ws[DIM * DIM];
    int t = threadIdx.x;
    for (int i = t; i < DIM * DIM / 4; i += 256)
        ((float4*)Ws)[i] = ((const float4*)W)[i];
    __syncthreads();

    int rg = blockIdx.x * 64 + (t >> 2);   // row-group of 4 rows
    int r0 = rg * 4;
    if (r0 >= n) return;
    int cg = (t & 3) * 16;                 // first column of this thread

    const float* xr[4];
#pragma unroll
    for (int r = 0; r < 4; r++) {
        int rowc = r0 + r;
        int rr = rowc < n ? rowc : (n - 1);
        xr[r] = tokens ? (emb + (size_t)__ldg(tokens + rr) * DIM)
                       : (X + (size_t)rr * DIM);
    }

    unsigned long long acc[4][8];
#pragma unroll
    for (int r = 0; r < 4; r++)
#pragma unroll
        for (int j = 0; j < 8; j++) acc[r][j] = 0ull;

#pragma unroll
    for (int k = 0; k < DIM; k += 4) {
        float4 xv0 = *(const float4*)(xr[0] + k);
        float4 xv1 = *(const float4*)(xr[1] + k);
        float4 xv2 = *(const float4*)(xr[2] + k);
        float4 xv3 = *(const float4*)(xr[3] + k);
#pragma unroll
        for (int kk = 0; kk < 4; kk++) {
            const ulonglong2* wp = (const ulonglong2*)(Ws + (k + kk) * DIM + cg);
            ulonglong2 wa = wp[0], wb = wp[1], wc = wp[2], wd = wp[3];
            unsigned long long x0 = pack2((&xv0.x)[kk]);
            unsigned long long x1 = pack2((&xv1.x)[kk]);
            unsigned long long x2 = pack2((&xv2.x)[kk]);
            unsigned long long x3 = pack2((&xv3.x)[kk]);
            fma2(acc[0][0], x0, wa.x); fma2(acc[0][1], x0, wa.y);
            fma2(acc[0][2], x0, wb.x); fma2(acc[0][3], x0, wb.y);
            fma2(acc[0][4], x0, wc.x); fma2(acc[0][5], x0, wc.y);
            fma2(acc[0][6], x0, wd.x); fma2(acc[0][7], x0, wd.y);
            fma2(acc[1][0], x1, wa.x); fma2(acc[1][1], x1, wa.y);
            fma2(acc[1][2], x1, wb.x); fma2(acc[1][3], x1, wb.y);
            fma2(acc[1][4], x1, wc.x); fma2(acc[1][5], x1, wc.y);
            fma2(acc[1][6], x1, wd.x); fma2(acc[1][7], x1, wd.y);
            fma2(acc[2][0], x2, wa.x); fma2(acc[2][1], x2, wa.y);
            fma2(acc[2][2], x2, wb.x); fma2(acc[2][3], x2, wb.y);
            fma2(acc[2][4], x2, wc.x); fma2(acc[2][5], x2, wc.y);
            fma2(acc[2][6], x2, wd.x); fma2(acc[2][7], x2, wd.y);
            fma2(acc[3][0], x3, wa.x); fma2(acc[3][1], x3, wa.y);
            fma2(acc[3][2], x3, wb.x); fma2(acc[3][3], x3, wb.y);
            fma2(acc[3][4], x3, wc.x); fma2(acc[3][5], x3, wc.y);
            fma2(acc[3][6], x3, wd.x); fma2(acc[3][7], x3, wd.y);
        }
    }

#pragma unroll
    for (int r = 0; r < 4; r++) {
        int rowc = r0 + r;
        if (rowc >= n) break;
        float dvs = g_dinv[rowc] * ZSCALE;
        uint32_t h[8];
#pragma unroll
        for (int j = 0; j < 8; j++) {
            float2 f = unpack2(acc[r][j]);
            h[j] = f2_to_h2(f.x * dvs, f.y * dvs);
        }
        uint32_t* zr = Z + (size_t)rowc * (DIM / 2) + (cg >> 1);
        *(uint4*)(zr)     = make_uint4(h[0], h[1], h[2], h[3]);
        *(uint4*)(zr + 4) = make_uint4(h[4], h[5], h[6], h[7]);
    }
}

// ---------------- gather: x_out[i] = relu(dinv[i]*(z[i]+sum z[src])/S + b) --
// warp per destination node; lane covers 2 feature dims as one half2 word
__global__ void k_gather(const uint32_t* __restrict__ Z, const float* __restrict__ b,
                         float* __restrict__ Xo, int n) {
    int w = (int)((blockIdx.x * blockDim.x + threadIdx.x) >> 5);
    if (w >= n) return;
    int lane = threadIdx.x & 31;
    int beg = g_rowptr[w], end = g_rowptr[w + 1];
    float2 acc = h2_to_f2(Z[(size_t)w * 32 + lane]);   // self loop
    for (int e0 = beg; e0 < end; e0 += 32) {
        int c = end - e0; if (c > 32) c = 32;
        int s = (lane < c) ? g_esrc[e0 + lane] : 0;
        int j = 0;
        for (; j + 4 <= c; j += 4) {
            int s0 = __shfl_sync(0xffffffffu, s, j);
            int s1 = __shfl_sync(0xffffffffu, s, j + 1);
            int s2 = __shfl_sync(0xffffffffu, s, j + 2);
            int s3 = __shfl_sync(0xffffffffu, s, j + 3);
            float2 v0 = h2_to_f2(Z[(size_t)s0 * 32 + lane]);
            float2 v1 = h2_to_f2(Z[(size_t)s1 * 32 + lane]);
            float2 v2 = h2_to_f2(Z[(size_t)s2 * 32 + lane]);
            float2 v3 = h2_to_f2(Z[(size_t)s3 * 32 + lane]);
            acc.x += (v0.x + v1.x) + (v2.x + v3.x);
            acc.y += (v0.y + v1.y) + (v2.y + v3.y);
        }
        for (; j < c; j++) {
            int sj = __shfl_sync(0xffffffffu, s, j);
            float2 v = h2_to_f2(Z[(size_t)sj * 32 + lane]);
            acc.x += v.x; acc.y += v.y;
        }
    }
    float dv = g_dinv[w] * ZUNSCALE;
    int col = lane * 2;
    float2 o;
    o.x = fmaxf(fmaf(dv, acc.x, __ldg(b + col)),     0.f);
    o.y = fmaxf(fmaf(dv, acc.y, __ldg(b + col + 1)), 0.f);
    ((float2*)Xo)[(size_t)w * 32 + lane] = o;
}

// ---------------- pooling (batch sorted): run-accumulate, flush on boundary -
__global__ void k_pool(const float* __restrict__ X, const int* __restrict__ batch, int n) {
    int w = (int)((blockIdx.x * blockDim.x + threadIdx.x) >> 5);
    int lane = threadIdx.x & 31;
    int base = w * 32;
    if (base >= n) return;
    int myb = (base + lane < n) ? batch[base + lane] : 0;
    const float2* xc = (const float2*)X;
    float2 s = make_float2(0.f, 0.f), m = make_float2(0.f, 0.f);
    int curg = __shfl_sync(0xffffffffu, myb, 0);
    int rc = 0;
    for (int j = 0; j < 32; j++) {
        int node = base + j;
        if (node >= n) break;
        int g = __shfl_sync(0xffffffffu, myb, j);
        if (g != curg) {
            atomicAdd(&g_clr.hsum[curg * DIM + lane * 2],     s.x);
            atomicAdd(&g_clr.hsum[curg * DIM + lane * 2 + 1], s.y);
            atomicMax((int*)&g_clr.hmax[curg * DIM + lane * 2],     __float_as_int(m.x));
            atomicMax((int*)&g_clr.hmax[curg * DIM + lane * 2 + 1], __float_as_int(m.y));
            if (lane == 0) atomicAdd(&g_clr.gcnt[curg], rc);
            s = make_float2(0.f, 0.f); m = make_float2(0.f, 0.f); rc = 0; curg = g;
        }
        float2 v = xc[(size_t)node * 32 + lane];
        s.x += v.x; s.y += v.y;
        m.x = fmaxf(m.x, v.x); m.y = fmaxf(m.y, v.y);
        rc++;
    }
    if (rc) {
        atomicAdd(&g_clr.hsum[curg * DIM + lane * 2],     s.x);
        atomicAdd(&g_clr.hsum[curg * DIM + lane * 2 + 1], s.y);
        atomicMax((int*)&g_clr.hmax[curg * DIM + lane * 2],     __float_as_int(m.x));
        atomicMax((int*)&g_clr.hmax[curg * DIM + lane * 2 + 1], __float_as_int(m.y));
        if (lane == 0) atomicAdd(&g_clr.gcnt[curg], rc);
    }
}

// ---------------- classifier head ------------------------------------------
__global__ void k_mlp(const float* __restrict__ Wc1, const float* __restrict__ bc1,
                      const float* __restrict__ Wc2, const float* __restrict__ bc2,
                      float* __restrict__ out) {
    __shared__ float h[2 * DIM];
    __shared__ float r[4];
    int g = blockIdx.x, t = threadIdx.x;  // 64 threads
    float cnt = fmaxf((float)g_clr.gcnt[g], 1.f);
    h[t]       = g_clr.hsum[g * DIM + t] / cnt;
    h[DIM + t] = g_clr.hmax[g * DIM + t];
    __syncthreads();
    float acc = bc1[t];
#pragma unroll 8
    for (int k = 0; k < 2 * DIM; k++) acc = fmaf(h[k], Wc1[k * DIM + t], acc);
    acc = fmaxf(acc, 0.f);
    float p0 = acc * Wc2[t * 2], p1 = acc * Wc2[t * 2 + 1];
#pragma unroll
    for (int o = 16; o; o >>= 1) {
        p0 += __shfl_down_sync(0xffffffffu, p0, o);
        p1 += __shfl_down_sync(0xffffffffu, p1, o);
    }
    if ((t & 31) == 0) { r[(t >> 5) * 2] = p0; r[(t >> 5) * 2 + 1] = p1; }
    __syncthreads();
    if (t == 0) {
        out[g * 2 + 0] = r[0] + r[2] + bc2[0];
        out[g * 2 + 1] = r[1] + r[3] + bc2[1];
    }
}

// ---------------- launcher --------------------------------------------------
extern "C" void kernel_launch(void* const* d_in, const int* in_sizes, int n_in,
                              void* d_out, int out_size) {
    const int*   tokens = (const int*)d_in[0];
    const int*   eidx   = (const int*)d_in[1];
    const int*   batch  = (const int*)d_in[2];
    const float* emb    = (const float*)d_in[3];
    const float* W0 = (const float*)d_in[4];  const float* b0 = (const float*)d_in[5];
    const float* W1 = (const float*)d_in[6];  const float* b1 = (const float*)d_in[7];
    const float* W2 = (const float*)d_in[8];  const float* b2 = (const float*)d_in[9];
    const float* Wc1 = (const float*)d_in[10]; const float* bc1 = (const float*)d_in[11];
    const float* Wc2 = (const float*)d_in[12]; const float* bc2 = (const float*)d_in[13];

    int n  = in_sizes[0];
    int e  = in_sizes[1] / 2;
    int Gn = out_size / 2;
    if (n > MAXN) n = MAXN;
    if (e > MAXE) e = MAXE;
    if (Gn > MAXG) Gn = MAXG;

    void *p_clr, *p_z, *p_xa, *p_xb;
    cudaGetSymbolAddress(&p_clr, g_clr);
    cudaGetSymbolAddress(&p_z,  g_z);
    cudaGetSymbolAddress(&p_xa, g_xa);
    cudaGetSymbolAddress(&p_xb, g_xb);
    uint32_t* Z = (uint32_t*)p_z;
    float* XA = (float*)p_xa;
    float* XB = (float*)p_xb;

    // One contiguous clear of cnt + hsum + hmax + gcnt
    cudaMemsetAsync(p_clr, 0, sizeof(ClearBlock));

    const int* src = eidx;
    const int* dst = eidx + e;

    int eb = (e + 255) / 256;
    int nb = (n + SCAN_CHUNK - 1) / SCAN_CHUNK;
    k_count<<<eb, 256>>>(dst, e);
    k_scan1<<<nb, 256>>>(n);
    k_scan2<<<1, 1>>>(nb, n);
    k_scan3<<<nb, 256>>>(n);
    k_dinv<<<(n + 255) / 256, 256>>>(n);
    k_scatter<<<eb, 256>>>(src, dst, e);

    int gb = (n + 255) / 256;  // gemm blocks (256 rows per block)
    int wb = (n + 7) / 8;      // warp-per-node blocks (8 warps/block)

    k_gemm<<<gb, 256>>>(nullptr, tokens, emb, W0, Z, n);
    k_gather<<<wb, 256>>>(Z, b0, XA, n);
    k_gemm<<<gb, 256>>>(XA, nullptr, nullptr, W1, Z, n);
    k_gather<<<wb, 256>>>(Z, b1, XB, n);
    k_gemm<<<gb, 256>>>(XB, nullptr, nullptr, W2, Z, n);
    k_gather<<<wb, 256>>>(Z, b2, XA, n);

    int pw = (n + 31) / 32;
    k_pool<<<(pw + 7) / 8, 256>>>(XA, batch, n);
    k_mlp<<<Gn, 64>>>(Wc1, bc1, Wc2, bc2, (float*)d_out);
}

// round 11
// speedup vs baseline: 2.1912x; 1.2173x over previous
#include <cuda_runtime.h>
#include <cuda_bf16.h>
#include <cuda_fp16.h>
#include <cstdint>

// Problem constants (fixed shapes for this problem)
#define MAXN 100000
#define MAXE 1600000
#define DIM  64
#define MAXG 512
#define SCAN_CHUNK 1024

#define ZSCALE   16384.0f          // 2^14: lifts values out of fp16 subnormal range
#define ZUNSCALE (1.0f / 16384.0f) // exact power of two

// ---------------- scratch (static device globals; no allocation allowed) ----
struct ClearBlock {
    int   cnt[MAXN];            // in-degree counts (excl self loop)
    float hsum[MAXG * DIM];
    float hmax[MAXG * DIM];
    int   gcnt[MAXG];
};
__device__ ClearBlock g_clr;

__device__ int      g_rowptr[MAXN + 1];   // CSR row pointers (by dst)
__device__ int      g_cursor[MAXN];       // scatter cursors
__device__ float    g_dinv[MAXN];         // deg^-0.5 (deg incl self loop)
__device__ int      g_esrc[MAXE];         // CSR column (src) indices
__device__ int      g_bsum[(MAXN + SCAN_CHUNK - 1) / SCAN_CHUNK + 1];
__device__ uint32_t g_z[(size_t)MAXN * (DIM / 2)];   // z scaled fp16 (half2 words)
__device__ uint32_t g_xh[(size_t)MAXN * (DIM / 2)];  // x scaled fp16 (half2 words)
__device__ float    g_xa[(size_t)MAXN * DIM];        // final features fp32 (pooling)
__device__ __half   g_wt[3][DIM * DIM];   // transposed fp16 weights Wt[n][k]

// ---------------- small helpers --------------------------------------------
__device__ __forceinline__ float2 h2_to_f2(uint32_t u) {
    __half2 h = *reinterpret_cast<__half2*>(&u);
    return __half22float2(h);
}
__device__ __forceinline__ uint32_t f2_to_h2(float a, float b) {
    __half2 h = __floats2half2_rn(a, b);
    return *reinterpret_cast<uint32_t*>(&h);
}

// ---------------- CSR build (coalesced multi-block ladder) ------------------
__global__ void k_count(const int* __restrict__ dst, int e) {
    int i = blockIdx.x * blockDim.x + threadIdx.x;
    if (i < e) atomicAdd(&g_clr.cnt[dst[i]], 1);
}

__global__ void k_scan1(int n) {  // per-1024-chunk sums
    int t = threadIdx.x;
    int base = blockIdx.x * SCAN_CHUNK + t * 4;
    int s = 0;
#pragma unroll
    for (int j = 0; j < 4; j++) if (base + j < n) s += g_clr.cnt[base + j];
#pragma unroll
    for (int o = 16; o; o >>= 1) s += __shfl_down_sync(0xffffffffu, s, o);
    __shared__ int ws[8];
    if ((t & 31) == 0) ws[t >> 5] = s;
    __syncthreads();
    if (t == 0) {
        int tot = 0;
#pragma unroll
        for (int i = 0; i < 8; i++) tot += ws[i];
        g_bsum[blockIdx.x] = tot;
    }
}

__global__ void k_scan2(int nb, int n) {  // tiny serial scan of chunk sums
    int run = 0;
    for (int i = 0; i < nb; i++) { int v = g_bsum[i]; g_bsum[i] = run; run += v; }
    g_rowptr[n] = run;
}

__global__ void k_scan3(int n) {  // per-chunk exclusive scan -> rowptr/cursor/dinv
    int t = threadIdx.x;
    int lane = t & 31, wid = t >> 5;
    int base = blockIdx.x * SCAN_CHUNK + t * 4;
    int c0 = (base + 0 < n) ? g_clr.cnt[base + 0] : 0;
    int c1 = (base + 1 < n) ? g_clr.cnt[base + 1] : 0;
    int c2 = (base + 2 < n) ? g_clr.cnt[base + 2] : 0;
    int c3 = (base + 3 < n) ? g_clr.cnt[base + 3] : 0;
    int ts = c0 + c1 + c2 + c3;
    int x = ts;
#pragma unroll
    for (int o = 1; o < 32; o <<= 1) {
        int y = __shfl_up_sync(0xffffffffu, x, o);
        if (lane >= o) x += y;
    }
    int wex = x - ts;  // exclusive within warp
    __shared__ int warpsums[8];
    if (lane == 31) warpsums[wid] = x;
    __syncthreads();
    int woff = 0;
    for (int i = 0; i < wid; i++) woff += warpsums[i];
    int off = g_bsum[blockIdx.x] + woff + wex;
    if (base + 0 < n) { g_rowptr[base + 0] = off;                g_cursor[base + 0] = off;                g_dinv[base + 0] = rsqrtf((float)(c0 + 1)); }
    if (base + 1 < n) { g_rowptr[base + 1] = off + c0;           g_cursor[base + 1] = off + c0;           g_dinv[base + 1] = rsqrtf((float)(c1 + 1)); }
    if (base + 2 < n) { g_rowptr[base + 2] = off + c0 + c1;      g_cursor[base + 2] = off + c0 + c1;      g_dinv[base + 2] = rsqrtf((float)(c2 + 1)); }
    if (base + 3 < n) { g_rowptr[base + 3] = off + c0 + c1 + c2; g_cursor[base + 3] = off + c0 + c1 + c2; g_dinv[base + 3] = rsqrtf((float)(c3 + 1)); }
}

__global__ void k_scatter(const int* __restrict__ src, const int* __restrict__ dst, int e) {
    int i = blockIdx.x * blockDim.x + threadIdx.x;
    if (i < e) {
        int d = dst[i];
        int p = atomicAdd(&g_cursor[d], 1);
        g_esrc[p] = src[i];
    }
}

// ---------------- weight prep: Wt[m][n][k] = fp16(W_m[k][n]) ----------------
__global__ void k_prepw(const float* __restrict__ W0, const float* __restrict__ W1,
                        const float* __restrict__ W2) {
    int i = blockIdx.x * blockDim.x + threadIdx.x;  // 0..12287
    if (i >= 3 * DIM * DIM) return;
    int m = i >> 12, r = i & 4095;
    int nn = r >> 6, kk = r & 63;
    const float* W = (m == 0) ? W0 : ((m == 1) ? W1 : W2);
    g_wt[m][nn * DIM + kk] = __float2half(W[kk * DIM + nn]);
}

// ---------------- tensor-core GEMM: z_h = dinv[i] * (xh_i @ W) --------------
// warp = 16-row tile; mma.m16n8k16 f16 inputs, f32 accum.
// xh carries a 2^14 scale (or emb rows are scaled on load for layer 0);
// output z_h keeps the 2^14 scale for the gather to remove.
__global__ void __launch_bounds__(256)
k_gemm_mma(const uint32_t* __restrict__ Xh, const int* __restrict__ tokens,
           const float* __restrict__ emb, const __half* __restrict__ Wt,
           uint32_t* __restrict__ Z, int n) {
    int warp = (int)((blockIdx.x * blockDim.x + threadIdx.x) >> 5);
    int lane = threadIdx.x & 31;
    int r0 = warp * 16;
    if (r0 >= n) return;
    int g = lane >> 2, t = lane & 3;

    int rA = r0 + g;     if (rA > n - 1) rA = n - 1;   // clamp for safe loads
    int rB = r0 + 8 + g; if (rB > n - 1) rB = n - 1;

    const uint32_t* wt32 = (const uint32_t*)Wt;  // Wt as [64][32] half2 words

    float acc[8][4];
#pragma unroll
    for (int j = 0; j < 8; j++) { acc[j][0] = acc[j][1] = acc[j][2] = acc[j][3] = 0.f; }

    const float* embA = nullptr; const float* embB = nullptr;
    const uint32_t* xA = nullptr; const uint32_t* xB = nullptr;
    if (tokens) {
        embA = emb + (size_t)__ldg(tokens + rA) * DIM;
        embB = emb + (size_t)__ldg(tokens + rB) * DIM;
    } else {
        xA = Xh + (size_t)rA * (DIM / 2);
        xB = Xh + (size_t)rB * (DIM / 2);
    }

#pragma unroll
    for (int kt = 0; kt < 4; kt++) {
        uint32_t a0, a1, a2, a3;
        if (tokens) {
            float2 eA0 = *(const float2*)(embA + 16 * kt + 2 * t);
            float2 eB0 = *(const float2*)(embB + 16 * kt + 2 * t);
            float2 eA1 = *(const float2*)(embA + 16 * kt + 8 + 2 * t);
            float2 eB1 = *(const float2*)(embB + 16 * kt + 8 + 2 * t);
            a0 = f2_to_h2(eA0.x * ZSCALE, eA0.y * ZSCALE);
            a1 = f2_to_h2(eB0.x * ZSCALE, eB0.y * ZSCALE);
            a2 = f2_to_h2(eA1.x * ZSCALE, eA1.y * ZSCALE);
            a3 = f2_to_h2(eB1.x * ZSCALE, eB1.y * ZSCALE);
        } else {
            a0 = xA[8 * kt + t];
            a1 = xB[8 * kt + t];
            a2 = xA[8 * kt + 4 + t];
            a3 = xB[8 * kt + 4 + t];
        }
#pragma unroll
        for (int j = 0; j < 8; j++) {
            uint32_t b0 = wt32[(8 * j + g) * 32 + 8 * kt + t];      // k = 16kt+2t
            uint32_t b1 = wt32[(8 * j + g) * 32 + 8 * kt + 4 + t];  // k = 16kt+8+2t
            asm volatile(
                "mma.sync.aligned.m16n8k16.row.col.f32.f16.f16.f32 "
                "{%0,%1,%2,%3}, {%4,%5,%6,%7}, {%8,%9}, {%0,%1,%2,%3};"
                : "+f"(acc[j][0]), "+f"(acc[j][1]), "+f"(acc[j][2]), "+f"(acc[j][3])
                : "r"(a0), "r"(a1), "r"(a2), "r"(a3), "r"(b0), "r"(b1));
        }
    }

    float s0 = g_dinv[rA];
    float s1 = g_dinv[rB];
    bool okA = (r0 + g) < n;
    bool okB = (r0 + 8 + g) < n;
    uint32_t* zA = Z + (size_t)(r0 + g) * (DIM / 2);
    uint32_t* zB = Z + (size_t)(r0 + 8 + g) * (DIM / 2);
#pragma unroll
    for (int j = 0; j < 8; j++) {
        if (okA) zA[4 * j + t] = f2_to_h2(acc[j][0] * s0, acc[j][1] * s0);
        if (okB) zB[4 * j + t] = f2_to_h2(acc[j][2] * s1, acc[j][3] * s1);
    }
}

// ---------------- gather: x_out[i] = relu(dinv[i]*(z[i]+sum z[src])/S + b) --
// warp per destination node; lane covers 2 feature dims as one half2 word.
// OUT_HALF: write scaled fp16 (feeds next GEMM); else fp32 (feeds pooling).
template <bool OUT_HALF>
__global__ void k_gather(const uint32_t* __restrict__ Z, const float* __restrict__ b,
                         void* __restrict__ Xo, int n) {
    int w = (int)((blockIdx.x * blockDim.x + threadIdx.x) >> 5);
    if (w >= n) return;
    int lane = threadIdx.x & 31;
    int beg = g_rowptr[w], end = g_rowptr[w + 1];
    float2 acc = h2_to_f2(Z[(size_t)w * 32 + lane]);   // self loop
    for (int e0 = beg; e0 < end; e0 += 32) {
        int c = end - e0; if (c > 32) c = 32;
        int s = (lane < c) ? g_esrc[e0 + lane] : 0;
        int j = 0;
        for (; j + 4 <= c; j += 4) {
            int s0 = __shfl_sync(0xffffffffu, s, j);
            int s1 = __shfl_sync(0xffffffffu, s, j + 1);
            int s2 = __shfl_sync(0xffffffffu, s, j + 2);
            int s3 = __shfl_sync(0xffffffffu, s, j + 3);
            float2 v0 = h2_to_f2(Z[(size_t)s0 * 32 + lane]);
            float2 v1 = h2_to_f2(Z[(size_t)s1 * 32 + lane]);
            float2 v2 = h2_to_f2(Z[(size_t)s2 * 32 + lane]);
            float2 v3 = h2_to_f2(Z[(size_t)s3 * 32 + lane]);
            acc.x += (v0.x + v1.x) + (v2.x + v3.x);
            acc.y += (v0.y + v1.y) + (v2.y + v3.y);
        }
        for (; j < c; j++) {
            int sj = __shfl_sync(0xffffffffu, s, j);
            float2 v = h2_to_f2(Z[(size_t)sj * 32 + lane]);
            acc.x += v.x; acc.y += v.y;
        }
    }
    float dv = g_dinv[w] * ZUNSCALE;
    int col = lane * 2;
    float ox = fmaxf(fmaf(dv, acc.x, __ldg(b + col)),     0.f);
    float oy = fmaxf(fmaf(dv, acc.y, __ldg(b + col + 1)), 0.f);
    if (OUT_HALF) {
        ((uint32_t*)Xo)[(size_t)w * 32 + lane] = f2_to_h2(ox * ZSCALE, oy * ZSCALE);
    } else {
        ((float2*)Xo)[(size_t)w * 32 + lane] = make_float2(ox, oy);
    }
}

// ---------------- pooling (batch sorted): run-accumulate, flush on boundary -
__global__ void k_pool(const float* __restrict__ X, const int* __restrict__ batch, int n) {
    int w = (int)((blockIdx.x * blockDim.x + threadIdx.x) >> 5);
    int lane = threadIdx.x & 31;
    int base = w * 32;
    if (base >= n) return;
    int myb = (base + lane < n) ? batch[base + lane] : 0;
    const float2* xc = (const float2*)X;
    float2 s = make_float2(0.f, 0.f), m = make_float2(0.f, 0.f);
    int curg = __shfl_sync(0xffffffffu, myb, 0);
    int rc = 0;
    for (int j = 0; j < 32; j++) {
        int node = base + j;
        if (node >= n) break;
        int g = __shfl_sync(0xffffffffu, myb, j);
        if (g != curg) {
            atomicAdd(&g_clr.hsum[curg * DIM + lane * 2],     s.x);
            atomicAdd(&g_clr.hsum[curg * DIM + lane * 2 + 1], s.y);
            atomicMax((int*)&g_clr.hmax[curg * DIM + lane * 2],     __float_as_int(m.x));
            atomicMax((int*)&g_clr.hmax[curg * DIM + lane * 2 + 1], __float_as_int(m.y));
            if (lane == 0) atomicAdd(&g_clr.gcnt[curg], rc);
            s = make_float2(0.f, 0.f); m = make_float2(0.f, 0.f); rc = 0; curg = g;
        }
        float2 v = xc[(size_t)node * 32 + lane];
        s.x += v.x; s.y += v.y;
        m.x = fmaxf(m.x, v.x); m.y = fmaxf(m.y, v.y);
        rc++;
    }
    if (rc) {
        atomicAdd(&g_clr.hsum[curg * DIM + lane * 2],     s.x);
        atomicAdd(&g_clr.hsum[curg * DIM + lane * 2 + 1], s.y);
        atomicMax((int*)&g_clr.hmax[curg * DIM + lane * 2],     __float_as_int(m.x));
        atomicMax((int*)&g_clr.hmax[curg * DIM + lane * 2 + 1], __float_as_int(m.y));
        if (lane == 0) atomicAdd(&g_clr.gcnt[curg], rc);
    }
}

// ---------------- classifier head ------------------------------------------
__global__ void k_mlp(const float* __restrict__ Wc1, const float* __restrict__ bc1,
                      const float* __restrict__ Wc2, const float* __restrict__ bc2,
                      float* __restrict__ out) {
    __shared__ float h[2 * DIM];
    __shared__ float r[4];
    int g = blockIdx.x, t = threadIdx.x;  // 64 threads
    float cnt = fmaxf((float)g_clr.gcnt[g], 1.f);
    h[t]       = g_clr.hsum[g * DIM + t] / cnt;
    h[DIM + t] = g_clr.hmax[g * DIM + t];
    __syncthreads();
    float acc = bc1[t];
#pragma unroll 8
    for (int k = 0; k < 2 * DIM; k++) acc = fmaf(h[k], Wc1[k * DIM + t], acc);
    acc = fmaxf(acc, 0.f);
    float p0 = acc * Wc2[t * 2], p1 = acc * Wc2[t * 2 + 1];
#pragma unroll
    for (int o = 16; o; o >>= 1) {
        p0 += __shfl_down_sync(0xffffffffu, p0, o);
        p1 += __shfl_down_sync(0xffffffffu, p1, o);
    }
    if ((t & 31) == 0) { r[(t >> 5) * 2] = p0; r[(t >> 5) * 2 + 1] = p1; }
    __syncthreads();
    if (t == 0) {
        out[g * 2 + 0] = r[0] + r[2] + bc2[0];
        out[g * 2 + 1] = r[1] + r[3] + bc2[1];
    }
}

// ---------------- launcher --------------------------------------------------
extern "C" void kernel_launch(void* const* d_in, const int* in_sizes, int n_in,
                              void* d_out, int out_size) {
    const int*   tokens = (const int*)d_in[0];
    const int*   eidx   = (const int*)d_in[1];
    const int*   batch  = (const int*)d_in[2];
    const float* emb    = (const float*)d_in[3];
    const float* W0 = (const float*)d_in[4];  const float* b0 = (const float*)d_in[5];
    const float* W1 = (const float*)d_in[6];  const float* b1 = (const float*)d_in[7];
    const float* W2 = (const float*)d_in[8];  const float* b2 = (const float*)d_in[9];
    const float* Wc1 = (const float*)d_in[10]; const float* bc1 = (const float*)d_in[11];
    const float* Wc2 = (const float*)d_in[12]; const float* bc2 = (const float*)d_in[13];

    int n  = in_sizes[0];
    int e  = in_sizes[1] / 2;
    int Gn = out_size / 2;
    if (n > MAXN) n = MAXN;
    if (e > MAXE) e = MAXE;
    if (Gn > MAXG) Gn = MAXG;

    void *p_clr, *p_z, *p_xh, *p_xa, *p_wt;
    cudaGetSymbolAddress(&p_clr, g_clr);
    cudaGetSymbolAddress(&p_z,  g_z);
    cudaGetSymbolAddress(&p_xh, g_xh);
    cudaGetSymbolAddress(&p_xa, g_xa);
    cudaGetSymbolAddress(&p_wt, g_wt);
    uint32_t* Z  = (uint32_t*)p_z;
    uint32_t* XH = (uint32_t*)p_xh;
    float* XA = (float*)p_xa;
    const __half* WT = (const __half*)p_wt;

    // One contiguous clear of cnt + hsum + hmax + gcnt
    cudaMemsetAsync(p_clr, 0, sizeof(ClearBlock));

    const int* src = eidx;
    const int* dst = eidx + e;

    int eb = (e + 255) / 256;
    int nb = (n + SCAN_CHUNK - 1) / SCAN_CHUNK;
    k_count<<<eb, 256>>>(dst, e);
    k_scan1<<<nb, 256>>>(n);
    k_scan2<<<1, 1>>>(nb, n);
    k_scan3<<<nb, 256>>>(n);
    k_scatter<<<eb, 256>>>(src, dst, e);
    k_prepw<<<(3 * DIM * DIM + 255) / 256, 256>>>(W0, W1, W2);

    int tiles = (n + 15) / 16;
    int mb = (tiles * 32 + 255) / 256;   // mma gemm blocks (8 warps each)
    int wb = (n + 7) / 8;                // gather: warp per node, 8 warps/block

    k_gemm_mma<<<mb, 256>>>(nullptr, tokens, emb, WT,            Z, n);
    k_gather<true ><<<wb, 256>>>(Z, b0, (void*)XH, n);
    k_gemm_mma<<<mb, 256>>>(XH, nullptr, nullptr, WT + DIM * DIM,     Z, n);
    k_gather<true ><<<wb, 256>>>(Z, b1, (void*)XH, n);
    k_gemm_mma<<<mb, 256>>>(XH, nullptr, nullptr, WT + 2 * DIM * DIM, Z, n);
    k_gather<false><<<wb, 256>>>(Z, b2, (void*)XA, n);

    int pw = (n + 31) / 32;
    k_pool<<<(pw + 7) / 8, 256>>>(XA, batch, n);
    k_mlp<<<Gn, 64>>>(Wc1, bc1, Wc2, bc2, (float*)d_out);
}

// round 16
// speedup vs baseline: 2.3460x; 1.0706x over previous
#include <cuda_runtime.h>
#include <cuda_bf16.h>
#include <cuda_fp16.h>
#include <cstdint>

// Problem constants (fixed shapes for this problem)
#define MAXN 100000
#define MAXE 1600000
#define DIM  64
#define MAXG 512
#define SCAN_CHUNK 1024

#define ZSCALE   16384.0f          // 2^14: lifts values out of fp16 subnormal range
#define ZUNSCALE (1.0f / 16384.0f) // exact power of two

// ---------------- scratch (static device globals; no allocation allowed) ----
struct ClearBlock {
    int   cnt[MAXN];            // in-degree counts (excl self loop)
    float hsum[MAXG * DIM];
    float hmax[MAXG * DIM];
    int   gcnt[MAXG];
};
__device__ ClearBlock g_clr;

__device__ int      g_rowptr[MAXN + 1];   // CSR row pointers (by dst)
__device__ int      g_cursor[MAXN];       // scatter cursors
__device__ float    g_dinv[MAXN];         // deg^-0.5 (deg incl self loop)
__device__ int      g_esrc[MAXE];         // CSR column (src) indices
__device__ int      g_bsum[(MAXN + SCAN_CHUNK - 1) / SCAN_CHUNK + 1];
__device__ uint32_t g_z[(size_t)MAXN * (DIM / 2)];   // z scaled fp16 (half2 words)
__device__ uint32_t g_xh[(size_t)MAXN * (DIM / 2)];  // x scaled fp16 (half2 words)
__device__ float    g_xa[(size_t)MAXN * DIM];        // final features fp32 (pooling)
__device__ __half   g_wt[3][DIM * DIM];   // transposed fp16 weights Wt[n][k]

// ---------------- small helpers --------------------------------------------
__device__ __forceinline__ float2 h2_to_f2(uint32_t u) {
    __half2 h = *reinterpret_cast<__half2*>(&u);
    return __half22float2(h);
}
__device__ __forceinline__ uint32_t f2_to_h2(float a, float b) {
    __half2 h = __floats2half2_rn(a, b);
    return *reinterpret_cast<uint32_t*>(&h);
}

// ---------------- CSR build (coalesced multi-block ladder) ------------------
__global__ void k_count(const int* __restrict__ dst, int e) {
    int i = blockIdx.x * blockDim.x + threadIdx.x;
    if (i < e) atomicAdd(&g_clr.cnt[dst[i]], 1);
}

__global__ void k_scan1(int n) {  // per-1024-chunk sums
    int t = threadIdx.x;
    int base = blockIdx.x * SCAN_CHUNK + t * 4;
    int s = 0;
#pragma unroll
    for (int j = 0; j < 4; j++) if (base + j < n) s += g_clr.cnt[base + j];
#pragma unroll
    for (int o = 16; o; o >>= 1) s += __shfl_down_sync(0xffffffffu, s, o);
    __shared__ int ws[8];
    if ((t & 31) == 0) ws[t >> 5] = s;
    __syncthreads();
    if (t == 0) {
        int tot = 0;
#pragma unroll
        for (int i = 0; i < 8; i++) tot += ws[i];
        g_bsum[blockIdx.x] = tot;
    }
}

__global__ void k_scan2(int nb, int n) {  // tiny serial scan of chunk sums
    int run = 0;
    for (int i = 0; i < nb; i++) { int v = g_bsum[i]; g_bsum[i] = run; run += v; }
    g_rowptr[n] = run;
}

__global__ void k_scan3(int n) {  // per-chunk exclusive scan -> rowptr/cursor/dinv
    int t = threadIdx.x;
    int lane = t & 31, wid = t >> 5;
    int base = blockIdx.x * SCAN_CHUNK + t * 4;
    int c0 = (base + 0 < n) ? g_clr.cnt[base + 0] : 0;
    int c1 = (base + 1 < n) ? g_clr.cnt[base + 1] : 0;
    int c2 = (base + 2 < n) ? g_clr.cnt[base + 2] : 0;
    int c3 = (base + 3 < n) ? g_clr.cnt[base + 3] : 0;
    int ts = c0 + c1 + c2 + c3;
    int x = ts;
#pragma unroll
    for (int o = 1; o < 32; o <<= 1) {
        int y = __shfl_up_sync(0xffffffffu, x, o);
        if (lane >= o) x += y;
    }
    int wex = x - ts;  // exclusive within warp
    __shared__ int warpsums[8];
    if (lane == 31) warpsums[wid] = x;
    __syncthreads();
    int woff = 0;
    for (int i = 0; i < wid; i++) woff += warpsums[i];
    int off = g_bsum[blockIdx.x] + woff + wex;
    if (base + 0 < n) { g_rowptr[base + 0] = off;                g_cursor[base + 0] = off;                g_dinv[base + 0] = rsqrtf((float)(c0 + 1)); }
    if (base + 1 < n) { g_rowptr[base + 1] = off + c0;           g_cursor[base + 1] = off + c0;           g_dinv[base + 1] = rsqrtf((float)(c1 + 1)); }
    if (base + 2 < n) { g_rowptr[base + 2] = off + c0 + c1;      g_cursor[base + 2] = off + c0 + c1;      g_dinv[base + 2] = rsqrtf((float)(c2 + 1)); }
    if (base + 3 < n) { g_rowptr[base + 3] = off + c0 + c1 + c2; g_cursor[base + 3] = off + c0 + c1 + c2; g_dinv[base + 3] = rsqrtf((float)(c3 + 1)); }
}

__global__ void k_scatter(const int* __restrict__ src, const int* __restrict__ dst, int e) {
    int i = blockIdx.x * blockDim.x + threadIdx.x;
    if (i < e) {
        int d = dst[i];
        int p = atomicAdd(&g_cursor[d], 1);
        g_esrc[p] = src[i];
    }
}

// ---------------- weight prep: Wt[m][n][k] = fp16(W_m[k][n]) ----------------
__global__ void k_prepw(const float* __restrict__ W0, const float* __restrict__ W1,
                        const float* __restrict__ W2) {
    int i = blockIdx.x * blockDim.x + threadIdx.x;  // 0..12287
    if (i >= 3 * DIM * DIM) return;
    int m = i >> 12, r = i & 4095;
    int nn = r >> 6, kk = r & 63;
    const float* W = (m == 0) ? W0 : ((m == 1) ? W1 : W2);
    g_wt[m][nn * DIM + kk] = __float2half(W[kk * DIM + nn]);
}

// ---------------- tensor-core GEMM: z_h = dinv[i] * (xh_i @ W) --------------
// warp = 16-row tile; mma.m16n8k16 f16 inputs, f32 accum.
// Wt staged into padded shared memory (stride 33 words) so the per-fragment
// reads sw[(8j+g)*33 + col] hit distinct banks for g=0..7 (stride-32-word
// rows would otherwise alias to one bank -> 8-way conflict / 8 wavefronts).
__global__ void __launch_bounds__(256)
k_gemm_mma(const uint32_t* __restrict__ Xh, const int* __restrict__ tokens,
           const float* __restrict__ emb, const __half* __restrict__ Wt,
           uint32_t* __restrict__ Z, int n) {
    __shared__ uint32_t sw[64 * 33];
    const uint32_t* wt32 = (const uint32_t*)Wt;  // Wt as [64][32] half2 words
    {
        int tid = threadIdx.x;
#pragma unroll
        for (int i = tid; i < 64 * 32; i += 256) {
            int row = i >> 5, col = i & 31;
            sw[row * 33 + col] = wt32[i];
        }
    }
    __syncthreads();

    int warp = (int)((blockIdx.x * blockDim.x + threadIdx.x) >> 5);
    int lane = threadIdx.x & 31;
    int r0 = warp * 16;
    if (r0 >= n) return;
    int g = lane >> 2, t = lane & 3;

    int rA = r0 + g;     if (rA > n - 1) rA = n - 1;   // clamp for safe loads
    int rB = r0 + 8 + g; if (rB > n - 1) rB = n - 1;

    float acc[8][4];
#pragma unroll
    for (int j = 0; j < 8; j++) { acc[j][0] = acc[j][1] = acc[j][2] = acc[j][3] = 0.f; }

    const float* embA = nullptr; const float* embB = nullptr;
    const uint32_t* xA = nullptr; const uint32_t* xB = nullptr;
    if (tokens) {
        embA = emb + (size_t)__ldg(tokens + rA) * DIM;
        embB = emb + (size_t)__ldg(tokens + rB) * DIM;
    } else {
        xA = Xh + (size_t)rA * (DIM / 2);
        xB = Xh + (size_t)rB * (DIM / 2);
    }

#pragma unroll
    for (int kt = 0; kt < 4; kt++) {
        uint32_t a0, a1, a2, a3;
        if (tokens) {
            float2 eA0 = *(const float2*)(embA + 16 * kt + 2 * t);
            float2 eB0 = *(const float2*)(embB + 16 * kt + 2 * t);
            float2 eA1 = *(const float2*)(embA + 16 * kt + 8 + 2 * t);
            float2 eB1 = *(const float2*)(embB + 16 * kt + 8 + 2 * t);
            a0 = f2_to_h2(eA0.x * ZSCALE, eA0.y * ZSCALE);
            a1 = f2_to_h2(eB0.x * ZSCALE, eB0.y * ZSCALE);
            a2 = f2_to_h2(eA1.x * ZSCALE, eA1.y * ZSCALE);
            a3 = f2_to_h2(eB1.x * ZSCALE, eB1.y * ZSCALE);
        } else {
            a0 = xA[8 * kt + t];
            a1 = xB[8 * kt + t];
            a2 = xA[8 * kt + 4 + t];
            a3 = xB[8 * kt + 4 + t];
        }
#pragma unroll
        for (int j = 0; j < 8; j++) {
            uint32_t b0 = sw[(8 * j + g) * 33 + 8 * kt + t];      // k = 16kt+2t
            uint32_t b1 = sw[(8 * j + g) * 33 + 8 * kt + 4 + t];  // k = 16kt+8+2t
            asm volatile(
                "mma.sync.aligned.m16n8k16.row.col.f32.f16.f16.f32 "
                "{%0,%1,%2,%3}, {%4,%5,%6,%7}, {%8,%9}, {%0,%1,%2,%3};"
                : "+f"(acc[j][0]), "+f"(acc[j][1]), "+f"(acc[j][2]), "+f"(acc[j][3])
                : "r"(a0), "r"(a1), "r"(a2), "r"(a3), "r"(b0), "r"(b1));
        }
    }

    float s0 = g_dinv[rA];
    float s1 = g_dinv[rB];
    bool okA = (r0 + g) < n;
    bool okB = (r0 + 8 + g) < n;
    uint32_t* zA = Z + (size_t)(r0 + g) * (DIM / 2);
    uint32_t* zB = Z + (size_t)(r0 + 8 + g) * (DIM / 2);
#pragma unroll
    for (int j = 0; j < 8; j++) {
        if (okA) zA[4 * j + t] = f2_to_h2(acc[j][0] * s0, acc[j][1] * s0);
        if (okB) zB[4 * j + t] = f2_to_h2(acc[j][2] * s1, acc[j][3] * s1);
    }
}

// ---------------- gather: x_out[i] = relu(dinv[i]*(z[i]+sum z[src])/S + b) --
// warp per destination node; lane covers 2 feature dims as one half2 word.
// OUT_HALF: write scaled fp16 (feeds next GEMM); else fp32 (feeds pooling).
template <bool OUT_HALF>
__global__ void k_gather(const uint32_t* __restrict__ Z, const float* __restrict__ b,
                         void* __restrict__ Xo, int n) {
    int w = (int)((blockIdx.x * blockDim.x + threadIdx.x) >> 5);
    if (w >= n) return;
    int lane = threadIdx.x & 31;
    int beg = g_rowptr[w], end = g_rowptr[w + 1];
    float2 acc = h2_to_f2(Z[(size_t)w * 32 + lane]);   // self loop
    for (int e0 = beg; e0 < end; e0 += 32) {
        int c = end - e0; if (c > 32) c = 32;
        int s = (lane < c) ? g_esrc[e0 + lane] : 0;
        int j = 0;
        for (; j + 4 <= c; j += 4) {
            int s0 = __shfl_sync(0xffffffffu, s, j);
            int s1 = __shfl_sync(0xffffffffu, s, j + 1);
            int s2 = __shfl_sync(0xffffffffu, s, j + 2);
            int s3 = __shfl_sync(0xffffffffu, s, j + 3);
            float2 v0 = h2_to_f2(Z[(size_t)s0 * 32 + lane]);
            float2 v1 = h2_to_f2(Z[(size_t)s1 * 32 + lane]);
            float2 v2 = h2_to_f2(Z[(size_t)s2 * 32 + lane]);
            float2 v3 = h2_to_f2(Z[(size_t)s3 * 32 + lane]);
            acc.x += (v0.x + v1.x) + (v2.x + v3.x);
            acc.y += (v0.y + v1.y) + (v2.y + v3.y);
        }
        for (; j < c; j++) {
            int sj = __shfl_sync(0xffffffffu, s, j);
            float2 v = h2_to_f2(Z[(size_t)sj * 32 + lane]);
            acc.x += v.x; acc.y += v.y;
        }
    }
    float dv = g_dinv[w] * ZUNSCALE;
    int col = lane * 2;
    float ox = fmaxf(fmaf(dv, acc.x, __ldg(b + col)),     0.f);
    float oy = fmaxf(fmaf(dv, acc.y, __ldg(b + col + 1)), 0.f);
    if (OUT_HALF) {
        ((uint32_t*)Xo)[(size_t)w * 32 + lane] = f2_to_h2(ox * ZSCALE, oy * ZSCALE);
    } else {
        ((float2*)Xo)[(size_t)w * 32 + lane] = make_float2(ox, oy);
    }
}

// ---------------- pooling (batch sorted): run-accumulate, flush on boundary -
__global__ void k_pool(const float* __restrict__ X, const int* __restrict__ batch, int n) {
    int w = (int)((blockIdx.x * blockDim.x + threadIdx.x) >> 5);
    int lane = threadIdx.x & 31;
    int base = w * 32;
    if (base >= n) return;
    int myb = (base + lane < n) ? batch[base + lane] : 0;
    const float2* xc = (const float2*)X;
    float2 s = make_float2(0.f, 0.f), m = make_float2(0.f, 0.f);
    int curg = __shfl_sync(0xffffffffu, myb, 0);
    int rc = 0;
    for (int j = 0; j < 32; j++) {
        int node = base + j;
        if (node >= n) break;
        int g = __shfl_sync(0xffffffffu, myb, j);
        if (g != curg) {
            atomicAdd(&g_clr.hsum[curg * DIM + lane * 2],     s.x);
            atomicAdd(&g_clr.hsum[curg * DIM + lane * 2 + 1], s.y);
            atomicMax((int*)&g_clr.hmax[curg * DIM + lane * 2],     __float_as_int(m.x));
            atomicMax((int*)&g_clr.hmax[curg * DIM + lane * 2 + 1], __float_as_int(m.y));
            if (lane == 0) atomicAdd(&g_clr.gcnt[curg], rc);
            s = make_float2(0.f, 0.f); m = make_float2(0.f, 0.f); rc = 0; curg = g;
        }
        float2 v = xc[(size_t)node * 32 + lane];
        s.x += v.x; s.y += v.y;
        m.x = fmaxf(m.x, v.x); m.y = fmaxf(m.y, v.y);
        rc++;
    }
    if (rc) {
        atomicAdd(&g_clr.hsum[curg * DIM + lane * 2],     s.x);
        atomicAdd(&g_clr.hsum[curg * DIM + lane * 2 + 1], s.y);
        atomicMax((int*)&g_clr.hmax[curg * DIM + lane * 2],     __float_as_int(m.x));
        atomicMax((int*)&g_clr.hmax[curg * DIM + lane * 2 + 1], __float_as_int(m.y));
        if (lane == 0) atomicAdd(&g_clr.gcnt[curg], rc);
    }
}

// ---------------- classifier head ------------------------------------------
__global__ void k_mlp(const float* __restrict__ Wc1, const float* __restrict__ bc1,
                      const float* __restrict__ Wc2, const float* __restrict__ bc2,
                      float* __restrict__ out) {
    __shared__ float h[2 * DIM];
    __shared__ float r[4];
    int g = blockIdx.x, t = threadIdx.x;  // 64 threads
    float cnt = fmaxf((float)g_clr.gcnt[g], 1.f);
    h[t]       = g_clr.hsum[g * DIM + t] / cnt;
    h[DIM + t] = g_clr.hmax[g * DIM + t];
    __syncthreads();
    float acc = bc1[t];
#pragma unroll 8
    for (int k = 0; k < 2 * DIM; k++) acc = fmaf(h[k], Wc1[k * DIM + t], acc);
    acc = fmaxf(acc, 0.f);
    float p0 = acc * Wc2[t * 2], p1 = acc * Wc2[t * 2 + 1];
#pragma unroll
    for (int o = 16; o; o >>= 1) {
        p0 += __shfl_down_sync(0xffffffffu, p0, o);
        p1 += __shfl_down_sync(0xffffffffu, p1, o);
    }
    if ((t & 31) == 0) { r[(t >> 5) * 2] = p0; r[(t >> 5) * 2 + 1] = p1; }
    __syncthreads();
    if (t == 0) {
        out[g * 2 + 0] = r[0] + r[2] + bc2[0];
        out[g * 2 + 1] = r[1] + r[3] + bc2[1];
    }
}

// ---------------- launcher --------------------------------------------------
extern "C" void kernel_launch(void* const* d_in, const int* in_sizes, int n_in,
                              void* d_out, int out_size) {
    const int*   tokens = (const int*)d_in[0];
    const int*   eidx   = (const int*)d_in[1];
    const int*   batch  = (const int*)d_in[2];
    const float* emb    = (const float*)d_in[3];
    const float* W0 = (const float*)d_in[4];  const float* b0 = (const float*)d_in[5];
    const float* W1 = (const float*)d_in[6];  const float* b1 = (const float*)d_in[7];
    const float* W2 = (const float*)d_in[8];  const float* b2 = (const float*)d_in[9];
    const float* Wc1 = (const float*)d_in[10]; const float* bc1 = (const float*)d_in[11];
    const float* Wc2 = (const float*)d_in[12]; const float* bc2 = (const float*)d_in[13];

    int n  = in_sizes[0];
    int e  = in_sizes[1] / 2;
    int Gn = out_size / 2;
    if (n > MAXN) n = MAXN;
    if (e > MAXE) e = MAXE;
    if (Gn > MAXG) Gn = MAXG;

    void *p_clr, *p_z, *p_xh, *p_xa, *p_wt;
    cudaGetSymbolAddress(&p_clr, g_clr);
    cudaGetSymbolAddress(&p_z,  g_z);
    cudaGetSymbolAddress(&p_xh, g_xh);
    cudaGetSymbolAddress(&p_xa, g_xa);
    cudaGetSymbolAddress(&p_wt, g_wt);
    uint32_t* Z  = (uint32_t*)p_z;
    uint32_t* XH = (uint32_t*)p_xh;
    float* XA = (float*)p_xa;
    const __half* WT = (const __half*)p_wt;

    // One contiguous clear of cnt + hsum + hmax + gcnt
    cudaMemsetAsync(p_clr, 0, sizeof(ClearBlock));

    const int* src = eidx;
    const int* dst = eidx + e;

    int eb = (e + 255) / 256;
    int nb = (n + SCAN_CHUNK - 1) / SCAN_CHUNK;
    k_count<<<eb, 256>>>(dst, e);
    k_scan1<<<nb, 256>>>(n);
    k_scan2<<<1, 1>>>(nb, n);
    k_scan3<<<nb, 256>>>(n);
    k_scatter<<<eb, 256>>>(src, dst, e);
    k_prepw<<<(3 * DIM * DIM + 255) / 256, 256>>>(W0, W1, W2);

    int tiles = (n + 15) / 16;
    int mb = (tiles + 7) / 8;            // mma gemm blocks (8 warps each)
    int wb = (n + 7) / 8;                // gather: warp per node, 8 warps/block

    k_gemm_mma<<<mb, 256>>>(nullptr, tokens, emb, WT,            Z, n);
    k_gather<true ><<<wb, 256>>>(Z, b0, (void*)XH, n);
    k_gemm_mma<<<mb, 256>>>(XH, nullptr, nullptr, WT + DIM * DIM,     Z, n);
    k_gather<true ><<<wb, 256>>>(Z, b1, (void*)XH, n);
    k_gemm_mma<<<mb, 256>>>(XH, nullptr, nullptr, WT + 2 * DIM * DIM, Z, n);
    k_gather<false><<<wb, 256>>>(Z, b2, (void*)XA, n);

    int pw = (n + 31) / 32;
    k_pool<<<(pw + 7) / 8, 256>>>(XA, batch, n);
    k_mlp<<<Gn, 64>>>(Wc1, bc1, Wc2, bc2, (float*)d_out);
}